// round 1
// baseline (speedup 1.0000x reference)
#include <cuda_runtime.h>

// FullyConnectedTensorProduct: B=2^20, MUL=8, DIM=32, 4 weight paths of 8x8x8.
// Strategy: one thread computes TWO batch elements using packed fp32x2
// (fma.rn.f32x2 -> FFMA2), weights duplicated (w,w) in shared memory and
// read via LDS.128 (two duplicated weights per load, broadcast).
// Scales ALPHA and ALPHA*INV_SQRT3 are folded into the shared weight copy.

typedef unsigned long long u64;

#define ALPHA_F     0.08838834764831845f   /* 1/sqrt(128) */
#define INV_SQRT3_F 0.5773502691896258f

static __device__ __forceinline__ u64 pk2(float lo, float hi) {
    u64 r;
    asm("mov.b64 %0, {%1, %2};"
        : "=l"(r) : "r"(__float_as_uint(lo)), "r"(__float_as_uint(hi)));
    return r;
}
static __device__ __forceinline__ void upk2(u64 v, float& lo, float& hi) {
    unsigned l_, h_;
    asm("mov.b64 {%0, %1}, %2;" : "=r"(l_), "=r"(h_) : "l"(v));
    lo = __uint_as_float(l_);
    hi = __uint_as_float(h_);
}
static __device__ __forceinline__ u64 ffma2(u64 a, u64 b, u64 c) {
    u64 d;
    asm("fma.rn.f32x2 %0, %1, %2, %3;" : "=l"(d) : "l"(a), "l"(b), "l"(c));
    return d;
}
static __device__ __forceinline__ u64 fmul2(u64 a, u64 b) {
    u64 d;
    asm("mul.rn.f32x2 %0, %1, %2;" : "=l"(d) : "l"(a), "l"(b));
    return d;
}

__global__ __launch_bounds__(256)
void fctp_kernel(const float* __restrict__ x1,
                 const float* __restrict__ x2,
                 const float* __restrict__ wt,
                 float* __restrict__ out,
                 int npair)
{
    // Duplicated, pre-scaled weights: wd[i] = (s*w[i], s*w[i]); 16 KB.
    __shared__ __align__(16) u64 wd[2048];
    for (int i = threadIdx.x; i < 2048; i += blockDim.x) {
        float s = ((i >> 9) == 1) ? (ALPHA_F * INV_SQRT3_F) : ALPHA_F;
        float v = wt[i] * s;
        wd[i] = pk2(v, v);
    }
    __syncthreads();

    int gid = blockIdx.x * blockDim.x + threadIdx.x;
    if (gid >= npair) return;

    const size_t base = (size_t)gid * 64;   // two consecutive rows of 32 floats

    // ---------------- load + pack inputs ----------------
    u64 s1[8], s2[8], v1[24], v2[24];
    {
        const float4* pa = (const float4*)(x1 + base);
        const float4* pb = (const float4*)(x2 + base);
#pragma unroll
        for (int j = 0; j < 2; j++) {
            float4 a = pa[j], b = pa[8 + j];
            s1[4*j+0] = pk2(a.x, b.x); s1[4*j+1] = pk2(a.y, b.y);
            s1[4*j+2] = pk2(a.z, b.z); s1[4*j+3] = pk2(a.w, b.w);
            float4 c = pb[j], d = pb[8 + j];
            s2[4*j+0] = pk2(c.x, d.x); s2[4*j+1] = pk2(c.y, d.y);
            s2[4*j+2] = pk2(c.z, d.z); s2[4*j+3] = pk2(c.w, d.w);
        }
#pragma unroll
        for (int j = 0; j < 6; j++) {
            float4 a = pa[2 + j], b = pa[10 + j];
            v1[4*j+0] = pk2(a.x, b.x); v1[4*j+1] = pk2(a.y, b.y);
            v1[4*j+2] = pk2(a.z, b.z); v1[4*j+3] = pk2(a.w, b.w);
            float4 c = pb[2 + j], d = pb[10 + j];
            v2[4*j+0] = pk2(c.x, d.x); v2[4*j+1] = pk2(c.y, d.y);
            v2[4*j+2] = pk2(c.z, d.z); v2[4*j+3] = pk2(c.w, d.w);
        }
    }

    u64 o0[8];
    u64 o1[24];
#pragma unroll
    for (int w = 0; w < 8; w++) o0[w] = 0ULL;
#pragma unroll
    for (int i = 0; i < 24; i++) o1[i] = 0ULL;

    // ---------------- W0: out0[w] += s2[v] * (sum_u s1[u]*W0[u,v,w]) ----------------
#pragma unroll
    for (int v = 0; v < 8; v++) {
        u64 a[8];
#pragma unroll
        for (int w = 0; w < 8; w++) a[w] = 0ULL;
#pragma unroll
        for (int u = 0; u < 8; u++) {
            const u64* wp = &wd[0 + u * 64 + v * 8];
#pragma unroll
            for (int w = 0; w < 8; w += 2) {
                ulonglong2 q = *(const ulonglong2*)(wp + w);
                a[w]     = ffma2(s1[u], q.x, a[w]);
                a[w + 1] = ffma2(s1[u], q.y, a[w + 1]);
            }
        }
#pragma unroll
        for (int w = 0; w < 8; w++) o0[w] = ffma2(s2[v], a[w], o0[w]);
    }

    // ---------------- W2: out1[w,k] += v2[v,k] * (sum_u s1[u]*W2[u,v,w]) ----------------
#pragma unroll
    for (int v = 0; v < 8; v++) {
        u64 a[8];
#pragma unroll
        for (int w = 0; w < 8; w++) a[w] = 0ULL;
#pragma unroll
        for (int u = 0; u < 8; u++) {
            const u64* wp = &wd[1024 + u * 64 + v * 8];
#pragma unroll
            for (int w = 0; w < 8; w += 2) {
                ulonglong2 q = *(const ulonglong2*)(wp + w);
                a[w]     = ffma2(s1[u], q.x, a[w]);
                a[w + 1] = ffma2(s1[u], q.y, a[w + 1]);
            }
        }
#pragma unroll
        for (int w = 0; w < 8; w++) {
#pragma unroll
            for (int k = 0; k < 3; k++)
                o1[w * 3 + k] = ffma2(v2[v * 3 + k], a[w], o1[w * 3 + k]);
        }
    }

    // ---------------- W1: out0[w] += (v1[u]·v2[v]) * W1'[u,v,w] ----------------
#pragma unroll
    for (int u = 0; u < 8; u++) {
#pragma unroll
        for (int v = 0; v < 8; v++) {
            u64 p = fmul2(v1[u * 3 + 0], v2[v * 3 + 0]);
            p = ffma2(v1[u * 3 + 1], v2[v * 3 + 1], p);
            p = ffma2(v1[u * 3 + 2], v2[v * 3 + 2], p);
            const u64* wp = &wd[512 + u * 64 + v * 8];
#pragma unroll
            for (int w = 0; w < 8; w += 2) {
                ulonglong2 q = *(const ulonglong2*)(wp + w);
                o0[w]     = ffma2(p, q.x, o0[w]);
                o0[w + 1] = ffma2(p, q.y, o0[w + 1]);
            }
        }
    }

    // ---------------- W3: out1[w,k] += v1[u,k] * (sum_v s2[v]*W3[u,v,w]) ----------------
#pragma unroll
    for (int u = 0; u < 8; u++) {
        u64 a[8];
#pragma unroll
        for (int w = 0; w < 8; w++) a[w] = 0ULL;
#pragma unroll
        for (int v = 0; v < 8; v++) {
            const u64* wp = &wd[1536 + u * 64 + v * 8];
#pragma unroll
            for (int w = 0; w < 8; w += 2) {
                ulonglong2 q = *(const ulonglong2*)(wp + w);
                a[w]     = ffma2(s2[v], q.x, a[w]);
                a[w + 1] = ffma2(s2[v], q.y, a[w + 1]);
            }
        }
#pragma unroll
        for (int w = 0; w < 8; w++) {
#pragma unroll
            for (int k = 0; k < 3; k++)
                o1[w * 3 + k] = ffma2(v1[u * 3 + k], a[w], o1[w * 3 + k]);
        }
    }

    // ---------------- unpack + store both rows ----------------
    float r0[32], r1[32];
#pragma unroll
    for (int w = 0; w < 8; w++) upk2(o0[w], r0[w], r1[w]);
#pragma unroll
    for (int i = 0; i < 24; i++) upk2(o1[i], r0[8 + i], r1[8 + i]);

    float4* q0 = (float4*)(out + base);
    float4* q1 = (float4*)(out + base + 32);
#pragma unroll
    for (int j = 0; j < 8; j++) {
        float4 t;
        t.x = r0[4*j+0]; t.y = r0[4*j+1]; t.z = r0[4*j+2]; t.w = r0[4*j+3];
        q0[j] = t;
    }
#pragma unroll
    for (int j = 0; j < 8; j++) {
        float4 t;
        t.x = r1[4*j+0]; t.y = r1[4*j+1]; t.z = r1[4*j+2]; t.w = r1[4*j+3];
        q1[j] = t;
    }
}

extern "C" void kernel_launch(void* const* d_in, const int* in_sizes, int n_in,
                              void* d_out, int out_size)
{
    const float* x1 = (const float*)d_in[0];
    const float* x2 = (const float*)d_in[1];
    const float* wt = (const float*)d_in[2];
    float* out = (float*)d_out;

    int nelem = out_size / 32;   // batch size
    int npair = nelem / 2;       // two elements per thread
    int threads = 256;
    int blocks = (npair + threads - 1) / threads;
    fctp_kernel<<<blocks, threads>>>(x1, x2, wt, out, npair);
}

// round 2
// speedup vs baseline: 1.2581x; 1.2581x over previous
#include <cuda_runtime.h>

// FullyConnectedTensorProduct: B=2^20, MUL=8, DIM=32, 4 weight paths of 8x8x8.
// One element per thread. SIMD axis of fma.rn.f32x2 packs ADJACENT w indices
// (weights contiguous in w -> natural LDS.128, no duplication) and k={0,1}
// for the vector outputs. Scalars are duplicated on the fly. o0 stored early
// to cut register pressure. Scales folded into shared weights.

typedef unsigned long long u64;

#define ALPHA_F     0.08838834764831845f   /* 1/sqrt(128) */
#define INV_SQRT3_F 0.5773502691896258f

static __device__ __forceinline__ u64 pk2(float lo, float hi) {
    u64 r;
    asm("mov.b64 %0, {%1, %2};"
        : "=l"(r) : "r"(__float_as_uint(lo)), "r"(__float_as_uint(hi)));
    return r;
}
static __device__ __forceinline__ u64 dup2(float x) { return pk2(x, x); }
static __device__ __forceinline__ void upk2(u64 v, float& lo, float& hi) {
    unsigned l_, h_;
    asm("mov.b64 {%0, %1}, %2;" : "=r"(l_), "=r"(h_) : "l"(v));
    lo = __uint_as_float(l_);
    hi = __uint_as_float(h_);
}
static __device__ __forceinline__ u64 ffma2(u64 a, u64 b, u64 c) {
    u64 d;
    asm("fma.rn.f32x2 %0, %1, %2, %3;" : "=l"(d) : "l"(a), "l"(b), "l"(c));
    return d;
}

__global__ __launch_bounds__(256, 2)
void fctp_kernel(const float* __restrict__ x1,
                 const float* __restrict__ x2,
                 const float* __restrict__ wt,
                 float* __restrict__ out,
                 int nelem)
{
    // Pre-scaled weights, natural layout [path][u][v][w], w contiguous. 8 KB.
    __shared__ __align__(16) float ws[2048];
    for (int i = threadIdx.x; i < 2048; i += blockDim.x) {
        float s = ((i >> 9) == 1) ? (ALPHA_F * INV_SQRT3_F) : ALPHA_F;
        ws[i] = wt[i] * s;
    }
    __syncthreads();

    int gid = blockIdx.x * blockDim.x + threadIdx.x;
    if (gid >= nelem) return;

    const size_t base = (size_t)gid * 32;

    // ---------------- load inputs (raw scalars) ----------------
    float s1[8], s2[8], v1[24], v2[24];
    {
        const float4* pa = (const float4*)(x1 + base);
        const float4* pb = (const float4*)(x2 + base);
#pragma unroll
        for (int j = 0; j < 2; j++) {
            float4 a = pa[j];
            s1[4*j+0] = a.x; s1[4*j+1] = a.y; s1[4*j+2] = a.z; s1[4*j+3] = a.w;
            float4 b = pb[j];
            s2[4*j+0] = b.x; s2[4*j+1] = b.y; s2[4*j+2] = b.z; s2[4*j+3] = b.w;
        }
#pragma unroll
        for (int j = 0; j < 6; j++) {
            float4 a = pa[2 + j];
            v1[4*j+0] = a.x; v1[4*j+1] = a.y; v1[4*j+2] = a.z; v1[4*j+3] = a.w;
            float4 b = pb[2 + j];
            v2[4*j+0] = b.x; v2[4*j+1] = b.y; v2[4*j+2] = b.z; v2[4*j+3] = b.w;
        }
    }

    // ======== out0 (w-pair packed): W0 then W1, store early ========
    u64 o0[4] = {0ULL, 0ULL, 0ULL, 0ULL};

    // W0: out0[w] += s2[v] * (sum_u s1[u] * W0[u,v,w])
#pragma unroll
    for (int v = 0; v < 8; v++) {
        u64 a[4] = {0ULL, 0ULL, 0ULL, 0ULL};
#pragma unroll
        for (int u = 0; u < 8; u++) {
            u64 su = dup2(s1[u]);
            const ulonglong2* wp = (const ulonglong2*)&ws[0 + u * 64 + v * 8];
            ulonglong2 q0 = wp[0], q1 = wp[1];
            a[0] = ffma2(su, q0.x, a[0]);
            a[1] = ffma2(su, q0.y, a[1]);
            a[2] = ffma2(su, q1.x, a[2]);
            a[3] = ffma2(su, q1.y, a[3]);
        }
        u64 sv = dup2(s2[v]);
#pragma unroll
        for (int i = 0; i < 4; i++) o0[i] = ffma2(sv, a[i], o0[i]);
    }

    // W1: out0[w] += (v1[u] . v2[v]) * W1'[u,v,w]
#pragma unroll
    for (int u = 0; u < 8; u++) {
#pragma unroll
        for (int v = 0; v < 8; v++) {
            float p = v1[u*3+0] * v2[v*3+0];
            p = fmaf(v1[u*3+1], v2[v*3+1], p);
            p = fmaf(v1[u*3+2], v2[v*3+2], p);
            u64 pd = dup2(p);
            const ulonglong2* wp = (const ulonglong2*)&ws[512 + u * 64 + v * 8];
            ulonglong2 q0 = wp[0], q1 = wp[1];
            o0[0] = ffma2(pd, q0.x, o0[0]);
            o0[1] = ffma2(pd, q0.y, o0[1]);
            o0[2] = ffma2(pd, q1.x, o0[2]);
            o0[3] = ffma2(pd, q1.y, o0[3]);
        }
    }

    // store out0 now (pairs are contiguous): frees o0 before W2/W3
    {
        float r[8];
        upk2(o0[0], r[0], r[1]); upk2(o0[1], r[2], r[3]);
        upk2(o0[2], r[4], r[5]); upk2(o0[3], r[6], r[7]);
        float4* q = (float4*)(out + base);
        q[0] = make_float4(r[0], r[1], r[2], r[3]);
        q[1] = make_float4(r[4], r[5], r[6], r[7]);
    }

    // ======== out1: o1a[w] packs (k0,k1), o1b[w] is k2 ========
    u64   o1a[8];
    float o1b[8];
#pragma unroll
    for (int w = 0; w < 8; w++) { o1a[w] = 0ULL; o1b[w] = 0.0f; }

    // W2: out1[w,k] += v2[v,k] * (sum_u s1[u] * W2[u,v,w])
#pragma unroll
    for (int v = 0; v < 8; v++) {
        u64 a[4] = {0ULL, 0ULL, 0ULL, 0ULL};
#pragma unroll
        for (int u = 0; u < 8; u++) {
            u64 su = dup2(s1[u]);
            const ulonglong2* wp = (const ulonglong2*)&ws[1024 + u * 64 + v * 8];
            ulonglong2 q0 = wp[0], q1 = wp[1];
            a[0] = ffma2(su, q0.x, a[0]);
            a[1] = ffma2(su, q0.y, a[1]);
            a[2] = ffma2(su, q1.x, a[2]);
            a[3] = ffma2(su, q1.y, a[3]);
        }
        float af[8];
        upk2(a[0], af[0], af[1]); upk2(a[1], af[2], af[3]);
        upk2(a[2], af[4], af[5]); upk2(a[3], af[6], af[7]);
        u64 vp = pk2(v2[v*3+0], v2[v*3+1]);
        float vz = v2[v*3+2];
#pragma unroll
        for (int w = 0; w < 8; w++) {
            o1a[w] = ffma2(vp, dup2(af[w]), o1a[w]);
            o1b[w] = fmaf(vz, af[w], o1b[w]);
        }
    }

    // W3: out1[w,k] += v1[u,k] * (sum_v s2[v] * W3[u,v,w])
#pragma unroll
    for (int u = 0; u < 8; u++) {
        u64 a[4] = {0ULL, 0ULL, 0ULL, 0ULL};
#pragma unroll
        for (int v = 0; v < 8; v++) {
            u64 sv = dup2(s2[v]);
            const ulonglong2* wp = (const ulonglong2*)&ws[1536 + u * 64 + v * 8];
            ulonglong2 q0 = wp[0], q1 = wp[1];
            a[0] = ffma2(sv, q0.x, a[0]);
            a[1] = ffma2(sv, q0.y, a[1]);
            a[2] = ffma2(sv, q1.x, a[2]);
            a[3] = ffma2(sv, q1.y, a[3]);
        }
        float af[8];
        upk2(a[0], af[0], af[1]); upk2(a[1], af[2], af[3]);
        upk2(a[2], af[4], af[5]); upk2(a[3], af[6], af[7]);
        u64 vp = pk2(v1[u*3+0], v1[u*3+1]);
        float vz = v1[u*3+2];
#pragma unroll
        for (int w = 0; w < 8; w++) {
            o1a[w] = ffma2(vp, dup2(af[w]), o1a[w]);
            o1b[w] = fmaf(vz, af[w], o1b[w]);
        }
    }

    // ---------------- store out1 (24 floats) ----------------
    {
        float r[24];
#pragma unroll
        for (int w = 0; w < 8; w++) {
            float k0, k1;
            upk2(o1a[w], k0, k1);
            r[w*3 + 0] = k0;
            r[w*3 + 1] = k1;
            r[w*3 + 2] = o1b[w];
        }
        float4* q = (float4*)(out + base + 8);
#pragma unroll
        for (int j = 0; j < 6; j++)
            q[j] = make_float4(r[4*j+0], r[4*j+1], r[4*j+2], r[4*j+3]);
    }
}

extern "C" void kernel_launch(void* const* d_in, const int* in_sizes, int n_in,
                              void* d_out, int out_size)
{
    const float* x1 = (const float*)d_in[0];
    const float* x2 = (const float*)d_in[1];
    const float* wt = (const float*)d_in[2];
    float* out = (float*)d_out;

    int nelem = out_size / 32;   // batch size
    int threads = 256;
    int blocks = (nelem + threads - 1) / threads;
    fctp_kernel<<<blocks, threads>>>(x1, x2, wt, out, nelem);
}